// round 2
// baseline (speedup 1.0000x reference)
#include <cuda_runtime.h>
#include <cstdint>

// Problem constants
#define B_ 64
#define L_ 512
#define P_ 64
#define A_ 16
#define F_ 80
#define D_ 512

// Scan kernel organization
#define CSZ 8       // cluster size (CTAs per cluster)
#define NCL 16      // number of clusters (B_/ROWS)
#define ROWS 4      // batch rows per cluster
#define COLS 64     // output columns per CTA (D_/CSZ)
#define THREADS 512

// Scratch (device globals: allocation-free rule)
__device__ float g_ci[B_ * L_ * D_];      // precomputed tanh(x@W_ci+b): 64 MB
__device__ float g_part[B_ * CSZ * L_];   // per-CTA cumulative output partials: 1 MB

// ---------------- f32x2 packed-FMA helpers (2x fp32 FMA throughput) ----------
__device__ __forceinline__ unsigned long long pk2(float lo, float hi) {
    unsigned long long r;
    asm("mov.b64 %0, {%1,%2};" : "=l"(r) : "f"(lo), "f"(hi));
    return r;
}
__device__ __forceinline__ void fma2(unsigned long long& d, unsigned long long a, unsigned long long b) {
    asm("fma.rn.f32x2 %0, %1, %2, %0;" : "+l"(d) : "l"(a), "l"(b));
}
__device__ __forceinline__ void upk2(float& lo, float& hi, unsigned long long v) {
    asm("mov.b64 {%0,%1}, %2;" : "=f"(lo), "=f"(hi) : "l"(v));
}

// ============================================================================
// Kernel 1: ci[b,l,d] = tanh( x[b,l,:] @ W_ci[:,d] + b_ci[d] ),  x = [obs|act]
// Tiled GEMM: 64 (bl) x 64 (d) tile per block, K = 80.
// ============================================================================
__global__ __launch_bounds__(256)
void k_ci(const float* __restrict__ obs, const float* __restrict__ act,
          const float* __restrict__ W, const float* __restrict__ bci)
{
    __shared__ float xs[64][81];   // padded
    __shared__ float ws[80][64];

    const int tid  = threadIdx.x;
    const int row0 = blockIdx.y * 64;   // bl tile
    const int d0   = blockIdx.x * 64;   // d  tile

    for (int idx = tid; idx < 64 * 80; idx += 256) {
        int r = idx / 80, c = idx % 80;
        int blg = row0 + r;
        int b = blg >> 9, l = blg & 511;
        float v = (c < 64) ? obs[(b * L_ + l) * P_ + c]
                           : act[(b * L_ + l) * A_ + (c - 64)];
        xs[r][c] = v;
    }
    for (int idx = tid; idx < 80 * 64; idx += 256) {
        int k = idx >> 6, d = idx & 63;
        ws[k][d] = W[k * D_ + d0 + d];
    }
    __syncthreads();

    const int tx = tid & 15, ty = tid >> 4;
    float acc[4][4] = {};
#pragma unroll
    for (int k = 0; k < 80; k++) {
        float a0 = xs[ty * 4 + 0][k];
        float a1 = xs[ty * 4 + 1][k];
        float a2 = xs[ty * 4 + 2][k];
        float a3 = xs[ty * 4 + 3][k];
        float4 bv = *(const float4*)&ws[k][tx * 4];
        acc[0][0] += a0 * bv.x; acc[0][1] += a0 * bv.y; acc[0][2] += a0 * bv.z; acc[0][3] += a0 * bv.w;
        acc[1][0] += a1 * bv.x; acc[1][1] += a1 * bv.y; acc[1][2] += a1 * bv.z; acc[1][3] += a1 * bv.w;
        acc[2][0] += a2 * bv.x; acc[2][1] += a2 * bv.y; acc[2][2] += a2 * bv.z; acc[2][3] += a2 * bv.w;
        acc[3][0] += a3 * bv.x; acc[3][1] += a3 * bv.y; acc[3][2] += a3 * bv.z; acc[3][3] += a3 * bv.w;
    }

    float bi0 = bci[d0 + tx * 4 + 0];
    float bi1 = bci[d0 + tx * 4 + 1];
    float bi2 = bci[d0 + tx * 4 + 2];
    float bi3 = bci[d0 + tx * 4 + 3];
#pragma unroll
    for (int ii = 0; ii < 4; ii++) {
        int blg = row0 + ty * 4 + ii;
        float4 o;
        o.x = tanhf(acc[ii][0] + bi0);
        o.y = tanhf(acc[ii][1] + bi1);
        o.z = tanhf(acc[ii][2] + bi2);
        o.w = tanhf(acc[ii][3] + bi3);
        *(float4*)&g_ci[blg * D_ + d0 + tx * 4] = o;
    }
}

// ============================================================================
// Kernel 2: the sequential scan. One 8-CTA cluster per group of 4 batch rows.
// CTA c owns columns [64c, 64c+64). R slice (512x64 fp32 = 128 KB) in SMEM.
// Per step: z[4,64] = h @ R_slice (f32x2 FMA, 8-way K-split over 512 threads),
// sigmoid, u = ci*ig, h_next = h + u broadcast to all cluster CTAs via DSMEM,
// incremental output partial accumulated per CTA. Double-buffered h -> one
// cluster barrier per step.
// ============================================================================
extern __shared__ float smem_f[];

__global__ void __cluster_dims__(CSZ, 1, 1) __launch_bounds__(THREADS, 1)
k_scan(const float* __restrict__ R, const float* __restrict__ b_ig,
       const float* __restrict__ W_out)
{
    float* Rs   = smem_f;                       // [512][64]   128 KB
    float* hbuf = Rs + D_ * COLS;               // [2][512][4]  16 KB  (h[i][b])
    float* pbuf = hbuf + 2 * D_ * ROWS;         // [8][64][4]    8 KB
    float* bias = pbuf + 8 * COLS * ROWS;       // [64]
    float* wsl  = bias + COLS;                  // [64]
    float* osum = wsl + COLS;                   // [8]

    const int tid = threadIdx.x;
    const int c   = blockIdx.x;          // cluster rank (column slice)
    const int b0  = blockIdx.y * ROWS;   // batch base
    const int j0  = c * COLS;            // column base

    // Load R slice: R row-major [i][j_global]; consecutive tid -> consecutive j
    for (int idx = tid; idx < D_ * COLS; idx += THREADS) {
        int i = idx >> 6, j = idx & 63;
        Rs[idx] = R[i * D_ + j0 + j];    // Rs[i*64 + j]
    }
    for (int idx = tid; idx < 2 * D_ * ROWS; idx += THREADS) hbuf[idx] = 0.0f;
    if (tid < COLS) {
        bias[tid] = b_ig[j0 + tid];
        wsl[tid]  = W_out[j0 + tid];
    }
    __syncthreads();
    asm volatile("barrier.cluster.arrive.aligned;" ::: "memory");
    asm volatile("barrier.cluster.wait.aligned;"   ::: "memory");

    const int ks = tid >> 6;        // K-split 0..7
    const int j  = tid & 63;        // column within slice
    const int bb = tid >> 6;        // (for tid<256) batch row 0..3
    const int jj = tid & 63;

    float racc = 0.0f;              // cumulative output partial (tid<4 only)

    for (int t = 0; t < L_; t++) {
        // Prefetch ci for this step (latency hidden under the matvec)
        float civ = 0.0f;
        if (tid < 256)
            civ = __ldg(&g_ci[((b0 + bb) * L_ + t) * D_ + j0 + jj]);

        const float* hc = hbuf + ((t & 1)       * (D_ * ROWS));
        float*       hn = hbuf + (((t + 1) & 1) * (D_ * ROWS));

        // z partials: thread (ks, j) covers i in [ks*64, ks*64+64), 4 batches
        unsigned long long a01 = 0, a23 = 0;
        const float* hbase = hc + ks * 64 * ROWS;       // h[i][b], 16B rows
        const float* rbase = Rs + ks * 64 * COLS + j;
#pragma unroll 16
        for (int ii = 0; ii < 64; ii++) {
            ulonglong2 hv = *(const ulonglong2*)(hbase + ii * 4); // (h0,h1),(h2,h3)
            float r = rbase[ii * 64];
            unsigned long long rr = pk2(r, r);
            fma2(a01, rr, hv.x);
            fma2(a23, rr, hv.y);
        }
        {
            float p0, p1, p2, p3;
            upk2(p0, p1, a01);
            upk2(p2, p3, a23);
            *(float4*)&pbuf[(ks * 64 + j) * 4] = make_float4(p0, p1, p2, p3);
        }
        __syncthreads();

        if (tid < 256) {
            // reduce the 8 K-split partials
            float z = bias[jj];
#pragma unroll
            for (int s = 0; s < 8; s++) z += pbuf[(s * 64 + jj) * 4 + bb];
            float ig = 1.0f / (1.0f + __expf(-z));
            float u  = civ * ig;

            const int jg = j0 + jj;
            float hval = hc[jg * 4 + bb] + u;

            // broadcast updated h element to every CTA's next-buffer (incl self)
            uint32_t laddr = (uint32_t)__cvta_generic_to_shared(&hn[jg * 4 + bb]);
            uint32_t hbits = __float_as_uint(hval);
#pragma unroll
            for (int p = 0; p < CSZ; p++) {
                uint32_t ra;
                asm volatile("mapa.shared::cluster.u32 %0, %1, %2;"
                             : "=r"(ra) : "r"(laddr), "r"(p));
                asm volatile("st.shared::cluster.b32 [%0], %1;"
                             :: "r"(ra), "r"(hbits));
            }

            // incremental output partial: sum_j u * W_out[j]
            float pp = u * wsl[jj];
#pragma unroll
            for (int off = 16; off > 0; off >>= 1)
                pp += __shfl_down_sync(0xFFFFFFFF, pp, off);
            if ((tid & 31) == 0) osum[tid >> 5] = pp;   // warp w -> batch w>>1
        }

        // one cluster barrier per step (double-buffered h)
        asm volatile("barrier.cluster.arrive.aligned;" ::: "memory");
        asm volatile("barrier.cluster.wait.aligned;"   ::: "memory");

        if (tid < 4) {
            racc += osum[tid * 2] + osum[tid * 2 + 1];
            g_part[(b0 + tid) * (CSZ * L_) + c * L_ + t] = racc;
        }
    }
}

// ============================================================================
// Kernel 3: out[b,t] = b_out + sum_c g_part[b][c][t]
// ============================================================================
__global__ __launch_bounds__(256)
void k_out(const float* __restrict__ b_out, float* __restrict__ out)
{
    int i = blockIdx.x * 256 + threadIdx.x;   // 0 .. 32767
    int b = i >> 9, t = i & 511;
    float s = b_out[0];
#pragma unroll
    for (int cc = 0; cc < CSZ; cc++) s += g_part[b * (CSZ * L_) + cc * L_ + t];
    out[i] = s;
}

// ============================================================================
extern "C" void kernel_launch(void* const* d_in, const int* in_sizes, int n_in,
                              void* d_out, int out_size)
{
    const float* obs  = (const float*)d_in[0];
    const float* act  = (const float*)d_in[1];
    const float* W_ci = (const float*)d_in[2];
    const float* b_ci = (const float*)d_in[3];
    const float* R    = (const float*)d_in[4];
    const float* bg   = (const float*)d_in[5];
    const float* W_o  = (const float*)d_in[6];
    const float* b_o  = (const float*)d_in[7];
    float* out = (float*)d_out;

    // Kernel 1: ci precompute
    k_ci<<<dim3(8, 512), 256>>>(obs, act, W_ci, b_ci);

    // Kernel 2: clustered sequential scan
    size_t smem = (size_t)(D_ * COLS + 2 * D_ * ROWS + 8 * COLS * ROWS
                           + COLS + COLS + 8) * sizeof(float);
    cudaFuncSetAttribute(k_scan, cudaFuncAttributeMaxDynamicSharedMemorySize, (int)smem);
    k_scan<<<dim3(CSZ, NCL), THREADS, smem>>>(R, bg, W_o);

    // Kernel 3: combine partials + bias
    k_out<<<128, 256>>>(b_o, out);
}

// round 4
// speedup vs baseline: 1.1483x; 1.1483x over previous
#include <cuda_runtime.h>
#include <cstdint>

// Problem constants
#define B_ 64
#define L_ 512
#define P_ 64
#define A_ 16
#define F_ 80
#define D_ 512

// Scan organization
#define CSZ 8       // CTAs per cluster (column split of R)
#define NCL 16      // clusters (B_/ROWS)
#define ROWS 4      // batch rows per cluster
#define COLS 64     // columns per CTA
#define KS 16       // K-split factor
#define KROWS (D_/KS)   // 32 rows per k-slice
#define THREADS 512

// Scratch
__device__ float g_ci[B_ * L_ * D_];      // tanh(x@W_ci+b)
__device__ float g_part[B_ * CSZ * L_];   // per-CTA cumulative output partials

// ---- f32x2 helpers --------------------------------------------------------
__device__ __forceinline__ unsigned long long pk2(float lo, float hi) {
    unsigned long long r;
    asm("mov.b64 %0, {%1,%2};" : "=l"(r) : "f"(lo), "f"(hi));
    return r;
}
__device__ __forceinline__ void fma2(unsigned long long& d, unsigned long long a, unsigned long long b) {
    asm("fma.rn.f32x2 %0, %1, %2, %0;" : "+l"(d) : "l"(a), "l"(b));
}
__device__ __forceinline__ void upk2(float& lo, float& hi, unsigned long long v) {
    asm("mov.b64 {%0,%1}, %2;" : "=f"(lo), "=f"(hi) : "l"(v));
}

// ---- cluster mbarrier helpers ---------------------------------------------
__device__ __forceinline__ void mbar_init(uint32_t addr, uint32_t cnt) {
    asm volatile("mbarrier.init.shared.b64 [%0], %1;" :: "r"(addr), "r"(cnt) : "memory");
}
__device__ __forceinline__ void mbar_arrive_rel_cluster(uint32_t addr) {
    asm volatile("mbarrier.arrive.release.cluster.shared::cluster.b64 _, [%0];"
                 :: "r"(addr) : "memory");
}
__device__ __forceinline__ void mbar_wait_acq_cluster(uint32_t addr, uint32_t parity) {
    uint32_t done;
    asm volatile(
        "{\n\t.reg .pred p;\n\t"
        "mbarrier.try_wait.parity.acquire.cluster.shared::cta.b64 p, [%1], %2;\n\t"
        "selp.b32 %0, 1, 0, p;\n\t}"
        : "=r"(done) : "r"(addr), "r"(parity) : "memory");
    if (!done) {
        asm volatile(
            "{\n\t.reg .pred P1;\n\t"
            "WL_%=:\n\t"
            "mbarrier.try_wait.parity.acquire.cluster.shared::cta.b64 P1, [%0], %1, 0x989680;\n\t"
            "@P1 bra.uni WD_%=;\n\t"
            "bra.uni WL_%=;\n\t"
            "WD_%=:\n\t}"
            :: "r"(addr), "r"(parity) : "memory");
    }
}
__device__ __forceinline__ void st_cluster_f4(uint32_t addr, float4 v) {
    asm volatile("st.shared::cluster.v4.b32 [%0], {%1,%2,%3,%4};"
                 :: "r"(addr), "f"(v.x), "f"(v.y), "f"(v.z), "f"(v.w) : "memory");
}

// ============================================================================
// Kernel 1: ci = tanh(x @ W_ci + b_ci)
// ============================================================================
__global__ __launch_bounds__(256)
void k_ci(const float* __restrict__ obs, const float* __restrict__ act,
          const float* __restrict__ W, const float* __restrict__ bci)
{
    __shared__ float xs[64][81];
    __shared__ float ws[80][64];

    const int tid  = threadIdx.x;
    const int row0 = blockIdx.y * 64;
    const int d0   = blockIdx.x * 64;

    for (int idx = tid; idx < 64 * 80; idx += 256) {
        int r = idx / 80, c = idx % 80;
        int blg = row0 + r;
        int b = blg >> 9, l = blg & 511;
        xs[r][c] = (c < 64) ? obs[(b * L_ + l) * P_ + c]
                            : act[(b * L_ + l) * A_ + (c - 64)];
    }
    for (int idx = tid; idx < 80 * 64; idx += 256) {
        int k = idx >> 6, d = idx & 63;
        ws[k][d] = W[k * D_ + d0 + d];
    }
    __syncthreads();

    const int tx = tid & 15, ty = tid >> 4;
    float acc[4][4] = {};
#pragma unroll
    for (int k = 0; k < 80; k++) {
        float a0 = xs[ty * 4 + 0][k];
        float a1 = xs[ty * 4 + 1][k];
        float a2 = xs[ty * 4 + 2][k];
        float a3 = xs[ty * 4 + 3][k];
        float4 bv = *(const float4*)&ws[k][tx * 4];
        acc[0][0] += a0 * bv.x; acc[0][1] += a0 * bv.y; acc[0][2] += a0 * bv.z; acc[0][3] += a0 * bv.w;
        acc[1][0] += a1 * bv.x; acc[1][1] += a1 * bv.y; acc[1][2] += a1 * bv.z; acc[1][3] += a1 * bv.w;
        acc[2][0] += a2 * bv.x; acc[2][1] += a2 * bv.y; acc[2][2] += a2 * bv.z; acc[2][3] += a2 * bv.w;
        acc[3][0] += a3 * bv.x; acc[3][1] += a3 * bv.y; acc[3][2] += a3 * bv.z; acc[3][3] += a3 * bv.w;
    }

    float bi0 = bci[d0 + tx * 4 + 0];
    float bi1 = bci[d0 + tx * 4 + 1];
    float bi2 = bci[d0 + tx * 4 + 2];
    float bi3 = bci[d0 + tx * 4 + 3];
#pragma unroll
    for (int ii = 0; ii < 4; ii++) {
        int blg = row0 + ty * 4 + ii;
        float4 o;
        o.x = tanhf(acc[ii][0] + bi0);
        o.y = tanhf(acc[ii][1] + bi1);
        o.z = tanhf(acc[ii][2] + bi2);
        o.w = tanhf(acc[ii][3] + bi3);
        *(float4*)&g_ci[blg * D_ + d0 + tx * 4] = o;
    }
}

// ============================================================================
// Kernel 2: the scan. 8-CTA cluster per 4 batch rows; triple-buffered h with
// per-step mbarrier sync (incremental per-buffer parity); vectorized DSMEM
// broadcast.
// ============================================================================
#define RS_OFF    0
#define HBUF_OFF  32768
#define PBUF_OFF  38912
#define HSTA_OFF  43008
#define BIAS_OFF  43264
#define WSL_OFF   43328
#define OSUM_OFF  43392
#define MBAR_BYTE (43424 * 4)
#define SMEM_BYTES (MBAR_BYTE + 64)

extern __shared__ float smem_f[];

__global__ void __cluster_dims__(CSZ, 1, 1) __launch_bounds__(THREADS, 1)
k_scan(const float* __restrict__ R, const float* __restrict__ b_ig,
       const float* __restrict__ W_out)
{
    float* Rs   = smem_f + RS_OFF;
    float* hbuf = smem_f + HBUF_OFF;
    float* pbuf = smem_f + PBUF_OFF;
    float* hsta = smem_f + HSTA_OFF;
    float* bias = smem_f + BIAS_OFF;
    float* wsl  = smem_f + WSL_OFF;
    float* osum = smem_f + OSUM_OFF;

    const uint32_t smem_u32 = (uint32_t)__cvta_generic_to_shared(smem_f);

    const int tid = threadIdx.x;
    const int c   = blockIdx.x;          // cluster rank / column slice
    const int b0  = blockIdx.y * ROWS;
    const int j0  = c * COLS;

    // ---- init ----
    for (int idx = tid; idx < D_ * COLS; idx += THREADS) {
        int i = idx >> 6, j = idx & 63;
        Rs[idx] = R[i * D_ + j0 + j];
    }
    for (int idx = tid; idx < 3 * D_ * ROWS; idx += THREADS) hbuf[idx] = 0.0f;
    if (tid < COLS) {
        bias[tid] = b_ig[j0 + tid];
        wsl[tid]  = W_out[j0 + tid];
    }
    if (tid == 0) {
        mbar_init(smem_u32 + MBAR_BYTE + 0,  CSZ * 64);
        mbar_init(smem_u32 + MBAR_BYTE + 8,  CSZ * 64);
        mbar_init(smem_u32 + MBAR_BYTE + 16, CSZ * 64);
    }
    __syncthreads();
    asm volatile("barrier.cluster.arrive.aligned;" ::: "memory");
    asm volatile("barrier.cluster.wait.aligned;"   ::: "memory");

    // Peer smem base addresses
    uint32_t peer_base[CSZ];
#pragma unroll
    for (int p = 0; p < CSZ; p++) {
        asm volatile("mapa.shared::cluster.u32 %0, %1, %2;"
                     : "=r"(peer_base[p]) : "r"(smem_u32), "r"(p));
    }

    // thread mapping for matvec: warp = k-slice, lane = column pair
    const int ks = tid >> 5;            // 0..15
    const int jp = tid & 31;            // cols 2jp, 2jp+1
    // thread mapping for reduce: tid<256
    const int jj = tid >> 2;            // 0..63
    const int bb = tid & 3;             // 0..3

    float racc = 0.0f;
    int cur = 0;
    uint32_t phases = 0;   // bit b = next wait parity for buffer b (incremental)

    for (int t = 0; t < L_; t++) {
        const int nxt = (cur == 2) ? 0 : cur + 1;

        // prefetch ci for this step (consumed after matvec)
        float civ = 0.0f;
        if (tid < 256)
            civ = __ldg(&g_ci[((b0 + bb) * L_ + t) * D_ + j0 + jj]);

        // wait for h(t) delivery (skip t=0: zeros written locally, no arrivals)
        if (t > 0) {
            mbar_wait_acq_cluster(smem_u32 + MBAR_BYTE + cur * 8,
                                  (phases >> cur) & 1u);
            phases ^= (1u << cur);
        }

        const float* hc = hbuf + cur * (D_ * ROWS);

        // ---- matvec: z partials for cols {2jp,2jp+1}, 4 batches ----
        {
            const ulonglong2* hvp = (const ulonglong2*)(hc + ks * KROWS * ROWS);
            const float* rp = Rs + ks * KROWS * COLS + jp * 2;
            unsigned long long a00 = 0, a01 = 0, a10 = 0, a11 = 0;
#pragma unroll 16
            for (int ii = 0; ii < KROWS; ii++) {
                ulonglong2 hv = hvp[ii];
                float2 rv = *(const float2*)(rp + ii * COLS);
                unsigned long long r0 = pk2(rv.x, rv.x);
                unsigned long long r1 = pk2(rv.y, rv.y);
                fma2(a00, r0, hv.x); fma2(a01, r0, hv.y);
                fma2(a10, r1, hv.x); fma2(a11, r1, hv.y);
            }
            float4 q0, q1;
            upk2(q0.x, q0.y, a00); upk2(q0.z, q0.w, a01);
            upk2(q1.x, q1.y, a10); upk2(q1.z, q1.w, a11);
            float* pb = pbuf + (ks * 32 + jp) * 8;
            *(float4*)(pb)     = q0;
            *(float4*)(pb + 4) = q1;
        }
        __syncthreads();

        // ---- reduce + gate + update ----
        if (tid < 256) {
            float z = bias[jj];
#pragma unroll
            for (int s = 0; s < KS; s++) z += pbuf[s * 256 + tid];
            float ig = 1.0f / (1.0f + __expf(-z));
            float u  = civ * ig;
            float hval = hc[(j0 + jj) * 4 + bb] + u;
            hsta[tid] = hval;

            float pp = u * wsl[jj];
            pp += __shfl_xor_sync(0xFFFFFFFF, pp, 4);
            pp += __shfl_xor_sync(0xFFFFFFFF, pp, 8);
            pp += __shfl_xor_sync(0xFFFFFFFF, pp, 16);
            if ((tid & 31) < 4)
                osum[(tid >> 5) * 4 + bb] = pp;
        }
        __syncthreads();

        // ---- broadcast h(t+1) slice to all cluster CTAs + arrive ----
        if (t + 1 < L_ && tid < 64) {
            float4 v = *(float4*)&hsta[tid * 4];
            uint32_t off  = (uint32_t)(HBUF_OFF + nxt * (D_ * ROWS) + (j0 + tid) * 4) * 4u;
            uint32_t moff = (uint32_t)(MBAR_BYTE + nxt * 8);
#pragma unroll
            for (int p = 0; p < CSZ; p++)
                st_cluster_f4(peer_base[p] + off, v);
#pragma unroll
            for (int p = 0; p < CSZ; p++)
                mbar_arrive_rel_cluster(peer_base[p] + moff);
        }

        // ---- cumulative output partial ----
        if (tid < 4) {
            float s = 0.0f;
#pragma unroll
            for (int w = 0; w < 8; w++) s += osum[w * 4 + tid];
            racc += s;
            g_part[(b0 + tid) * (CSZ * L_) + c * L_ + t] = racc;
        }

        cur = nxt;
    }

    asm volatile("barrier.cluster.arrive.aligned;" ::: "memory");
    asm volatile("barrier.cluster.wait.aligned;"   ::: "memory");
}

// ============================================================================
// Kernel 3: out[b,t] = b_out + sum_c g_part[b][c][t]
// ============================================================================
__global__ __launch_bounds__(256)
void k_out(const float* __restrict__ b_out, float* __restrict__ out)
{
    int i = blockIdx.x * 256 + threadIdx.x;
    int b = i >> 9, t = i & 511;
    float s = b_out[0];
#pragma unroll
    for (int cc = 0; cc < CSZ; cc++) s += g_part[b * (CSZ * L_) + cc * L_ + t];
    out[i] = s;
}

// ============================================================================
extern "C" void kernel_launch(void* const* d_in, const int* in_sizes, int n_in,
                              void* d_out, int out_size)
{
    const float* obs  = (const float*)d_in[0];
    const float* act  = (const float*)d_in[1];
    const float* W_ci = (const float*)d_in[2];
    const float* b_ci = (const float*)d_in[3];
    const float* R    = (const float*)d_in[4];
    const float* bg   = (const float*)d_in[5];
    const float* W_o  = (const float*)d_in[6];
    const float* b_o  = (const float*)d_in[7];
    float* out = (float*)d_out;

    k_ci<<<dim3(8, 512), 256>>>(obs, act, W_ci, b_ci);

    cudaFuncSetAttribute(k_scan, cudaFuncAttributeMaxDynamicSharedMemorySize, SMEM_BYTES);
    k_scan<<<dim3(CSZ, NCL), THREADS, SMEM_BYTES>>>(R, bg, W_o);

    k_out<<<128, 256>>>(b_o, out);
}

// round 5
// speedup vs baseline: 1.2436x; 1.0830x over previous
#include <cuda_runtime.h>
#include <cstdint>

// Problem constants
#define B_ 64
#define L_ 512
#define P_ 64
#define A_ 16
#define F_ 80
#define D_ 512

// Scan organization
#define CSZ 8       // CTAs per cluster (column split of R)
#define NCL 16      // clusters (B_/ROWS)
#define ROWS 4      // batch rows per cluster
#define COLS 64     // columns per CTA
#define KROWS 32    // rows per warp k-slice (16 warps)
#define THREADS 512

// Scratch
__device__ float g_ci[B_ * L_ * D_];      // tanh(x@W_ci+b)
__device__ float g_part[B_ * CSZ * L_];   // per-CTA cumulative output partials

// ---- f32x2 helpers --------------------------------------------------------
__device__ __forceinline__ unsigned long long pk2(float lo, float hi) {
    unsigned long long r;
    asm("mov.b64 %0, {%1,%2};" : "=l"(r) : "f"(lo), "f"(hi));
    return r;
}
__device__ __forceinline__ void fma2(unsigned long long& d, unsigned long long a, unsigned long long b) {
    asm("fma.rn.f32x2 %0, %1, %2, %0;" : "+l"(d) : "l"(a), "l"(b));
}
__device__ __forceinline__ void upk2(float& lo, float& hi, unsigned long long v) {
    asm("mov.b64 {%0,%1}, %2;" : "=f"(lo), "=f"(hi) : "l"(v));
}

// ---- cluster mbarrier helpers ---------------------------------------------
__device__ __forceinline__ void mbar_init(uint32_t addr, uint32_t cnt) {
    asm volatile("mbarrier.init.shared.b64 [%0], %1;" :: "r"(addr), "r"(cnt) : "memory");
}
__device__ __forceinline__ void mbar_arrive_rel_cluster(uint32_t addr) {
    asm volatile("mbarrier.arrive.release.cluster.shared::cluster.b64 _, [%0];"
                 :: "r"(addr) : "memory");
}
__device__ __forceinline__ void mbar_wait_acq_cluster(uint32_t addr, uint32_t parity) {
    uint32_t done;
    asm volatile(
        "{\n\t.reg .pred p;\n\t"
        "mbarrier.try_wait.parity.acquire.cluster.shared::cta.b64 p, [%1], %2;\n\t"
        "selp.b32 %0, 1, 0, p;\n\t}"
        : "=r"(done) : "r"(addr), "r"(parity) : "memory");
    if (!done) {
        asm volatile(
            "{\n\t.reg .pred P1;\n\t"
            "WL_%=:\n\t"
            "mbarrier.try_wait.parity.acquire.cluster.shared::cta.b64 P1, [%0], %1, 0x989680;\n\t"
            "@P1 bra.uni WD_%=;\n\t"
            "bra.uni WL_%=;\n\t"
            "WD_%=:\n\t}"
            :: "r"(addr), "r"(parity) : "memory");
    }
}
__device__ __forceinline__ void st_cluster_f4(uint32_t addr, float4 v) {
    asm volatile("st.shared::cluster.v4.b32 [%0], {%1,%2,%3,%4};"
                 :: "r"(addr), "f"(v.x), "f"(v.y), "f"(v.z), "f"(v.w) : "memory");
}

// ============================================================================
// Kernel 1: ci = tanh(x @ W_ci + b_ci)
// ============================================================================
__global__ __launch_bounds__(256)
void k_ci(const float* __restrict__ obs, const float* __restrict__ act,
          const float* __restrict__ W, const float* __restrict__ bci)
{
    __shared__ float xs[64][81];
    __shared__ float ws[80][64];

    const int tid  = threadIdx.x;
    const int row0 = blockIdx.y * 64;
    const int d0   = blockIdx.x * 64;

    for (int idx = tid; idx < 64 * 80; idx += 256) {
        int r = idx / 80, c = idx % 80;
        int blg = row0 + r;
        int b = blg >> 9, l = blg & 511;
        xs[r][c] = (c < 64) ? obs[(b * L_ + l) * P_ + c]
                            : act[(b * L_ + l) * A_ + (c - 64)];
    }
    for (int idx = tid; idx < 80 * 64; idx += 256) {
        int k = idx >> 6, d = idx & 63;
        ws[k][d] = W[k * D_ + d0 + d];
    }
    __syncthreads();

    const int tx = tid & 15, ty = tid >> 4;
    float acc[4][4] = {};
#pragma unroll
    for (int k = 0; k < 80; k++) {
        float a0 = xs[ty * 4 + 0][k];
        float a1 = xs[ty * 4 + 1][k];
        float a2 = xs[ty * 4 + 2][k];
        float a3 = xs[ty * 4 + 3][k];
        float4 bv = *(const float4*)&ws[k][tx * 4];
        acc[0][0] += a0 * bv.x; acc[0][1] += a0 * bv.y; acc[0][2] += a0 * bv.z; acc[0][3] += a0 * bv.w;
        acc[1][0] += a1 * bv.x; acc[1][1] += a1 * bv.y; acc[1][2] += a1 * bv.z; acc[1][3] += a1 * bv.w;
        acc[2][0] += a2 * bv.x; acc[2][1] += a2 * bv.y; acc[2][2] += a2 * bv.z; acc[2][3] += a2 * bv.w;
        acc[3][0] += a3 * bv.x; acc[3][1] += a3 * bv.y; acc[3][2] += a3 * bv.z; acc[3][3] += a3 * bv.w;
    }

    float bi0 = bci[d0 + tx * 4 + 0];
    float bi1 = bci[d0 + tx * 4 + 1];
    float bi2 = bci[d0 + tx * 4 + 2];
    float bi3 = bci[d0 + tx * 4 + 3];
#pragma unroll
    for (int ii = 0; ii < 4; ii++) {
        int blg = row0 + ty * 4 + ii;
        float4 o;
        o.x = tanhf(acc[ii][0] + bi0);
        o.y = tanhf(acc[ii][1] + bi1);
        o.z = tanhf(acc[ii][2] + bi2);
        o.w = tanhf(acc[ii][3] + bi3);
        *(float4*)&g_ci[blg * D_ + d0 + tx * 4] = o;
    }
}

// ============================================================================
// Kernel 2: the scan. R in REGISTERS (64 floats/thread). Triple-buffered h,
// 8 aggregated release-arrives per barrier per step, 512-wide DSMEM stores.
//
// SMEM (floats):
//   hbuf [0, 6144)       3 x 512 x 4
//   pbuf [6144, 10240)   512 x 8
//   hsta [10240, 10496)  64 x 4
//   bias [10496, 10560)
//   wsl  [10560, 10624)
//   osum [10624, 10656)
//   mbar @ byte 42624 (3 x 8 B)
// ============================================================================
#define HBUF_OFF  0
#define PBUF_OFF  6144
#define HSTA_OFF  10240
#define BIAS_OFF  10496
#define WSL_OFF   10560
#define OSUM_OFF  10624
#define MBAR_BYTE 42624
#define SMEM_BYTES (MBAR_BYTE + 64)

extern __shared__ float smem_f[];

__global__ void __cluster_dims__(CSZ, 1, 1) __launch_bounds__(THREADS, 1)
k_scan(const float* __restrict__ R, const float* __restrict__ b_ig,
       const float* __restrict__ W_out)
{
    float* hbuf = smem_f + HBUF_OFF;
    float* pbuf = smem_f + PBUF_OFF;
    float* hsta = smem_f + HSTA_OFF;
    float* bias = smem_f + BIAS_OFF;
    float* wsl  = smem_f + WSL_OFF;
    float* osum = smem_f + OSUM_OFF;

    const uint32_t smem_u32 = (uint32_t)__cvta_generic_to_shared(smem_f);

    const int tid = threadIdx.x;
    const int c   = blockIdx.x;          // cluster rank / column slice
    const int b0  = blockIdx.y * ROWS;
    const int j0  = c * COLS;

    const int ks = tid >> 5;             // warp = k-slice (0..15)
    const int jp = tid & 31;             // column pair (cols 2jp, 2jp+1)
    const int jj = tid >> 2;             // reduce mapping (tid<256)
    const int bb = tid & 3;

    // ---- R slice into registers: rows [ks*32, ks*32+32), cols {2jp, 2jp+1} ----
    float rx[KROWS], ry[KROWS];
    {
        const float* rg = R + j0 + 2 * jp;
#pragma unroll
        for (int ii = 0; ii < KROWS; ii++) {
            float2 v = *(const float2*)(rg + (ks * KROWS + ii) * D_);
            rx[ii] = v.x; ry[ii] = v.y;
        }
    }

    // ---- init smem ----
    for (int idx = tid; idx < 3 * D_ * ROWS; idx += THREADS) hbuf[idx] = 0.0f;
    if (tid < COLS) {
        bias[tid] = b_ig[j0 + tid];
        wsl[tid]  = W_out[j0 + tid];
    }
    if (tid == 0) {
        mbar_init(smem_u32 + MBAR_BYTE + 0,  CSZ);
        mbar_init(smem_u32 + MBAR_BYTE + 8,  CSZ);
        mbar_init(smem_u32 + MBAR_BYTE + 16, CSZ);
    }
    __syncthreads();
    asm volatile("barrier.cluster.arrive.aligned;" ::: "memory");
    asm volatile("barrier.cluster.wait.aligned;"   ::: "memory");

    // Peer smem bases (all threads compute; tid0 uses the array, storers use one)
    uint32_t peer_base[CSZ];
#pragma unroll
    for (int p = 0; p < CSZ; p++) {
        asm volatile("mapa.shared::cluster.u32 %0, %1, %2;"
                     : "=r"(peer_base[p]) : "r"(smem_u32), "r"(p));
    }
    const uint32_t my_store_base = peer_base[tid >> 6];   // peer for this thread's store
    const int jq = tid & 63;                              // float4 index it delivers

    float racc = 0.0f;
    int cur = 0;
    uint32_t phases = 0;   // bit b = next wait parity for buffer b

    for (int t = 0; t < L_; t++) {
        const int nxt = (cur == 2) ? 0 : cur + 1;

        // prefetch ci (consumed after matvec)
        float civ = 0.0f;
        if (tid < 256)
            civ = __ldg(&g_ci[((b0 + bb) * L_ + t) * D_ + j0 + jj]);

        // wait for h(t) delivery (skip t=0: zeros written locally)
        if (t > 0) {
            mbar_wait_acq_cluster(smem_u32 + MBAR_BYTE + cur * 8,
                                  (phases >> cur) & 1u);
            phases ^= (1u << cur);
        }

        const float* hc = hbuf + cur * (D_ * ROWS);

        // ---- matvec: R from registers, h broadcast from smem ----
        {
            const ulonglong2* hvp = (const ulonglong2*)(hc + ks * KROWS * ROWS);
            unsigned long long a00 = 0, a01 = 0, a10 = 0, a11 = 0;
#pragma unroll
            for (int ii = 0; ii < KROWS; ii++) {
                ulonglong2 hv = hvp[ii];                  // h[i][0..3], 16B bcast
                unsigned long long r0 = pk2(rx[ii], rx[ii]);
                unsigned long long r1 = pk2(ry[ii], ry[ii]);
                fma2(a00, r0, hv.x); fma2(a01, r0, hv.y);
                fma2(a10, r1, hv.x); fma2(a11, r1, hv.y);
            }
            float4 q0, q1;
            upk2(q0.x, q0.y, a00); upk2(q0.z, q0.w, a01);
            upk2(q1.x, q1.y, a10); upk2(q1.z, q1.w, a11);
            float* pb = pbuf + (ks * 32 + jp) * 8;
            *(float4*)(pb)     = q0;
            *(float4*)(pb + 4) = q1;
        }
        __syncthreads();

        // ---- reduce + gate + update ----
        if (tid < 256) {
            float z = bias[jj];
#pragma unroll
            for (int s = 0; s < 16; s++) z += pbuf[s * 256 + tid];
            float ig = 1.0f / (1.0f + __expf(-z));
            float u  = civ * ig;
            float hval = hc[(j0 + jj) * 4 + bb] + u;
            hsta[tid] = hval;

            float pp = u * wsl[jj];
            pp += __shfl_xor_sync(0xFFFFFFFF, pp, 4);
            pp += __shfl_xor_sync(0xFFFFFFFF, pp, 8);
            pp += __shfl_xor_sync(0xFFFFFFFF, pp, 16);
            if ((tid & 31) < 4)
                osum[(tid >> 5) * 4 + bb] = pp;
        }
        __syncthreads();

        // ---- broadcast h(t+1): each of 512 threads delivers ONE float4 ----
        if (t + 1 < L_) {
            float4 v = *(float4*)&hsta[jq * 4];
            uint32_t off = (uint32_t)(HBUF_OFF + nxt * (D_ * ROWS) + (j0 + jq) * 4) * 4u;
            st_cluster_f4(my_store_base + off, v);
        }

        // ---- cumulative output partial (overlaps with stores) ----
        if (tid < 4) {
            float s = 0.0f;
#pragma unroll
            for (int w = 0; w < 8; w++) s += osum[w * 4 + tid];
            racc += s;
            g_part[(b0 + tid) * (CSZ * L_) + c * L_ + t] = racc;
        }
        __syncthreads();

        // ---- aggregated release: ONE thread arrives on all 8 peer barriers ----
        if (t + 1 < L_ && tid == 0) {
            uint32_t moff = (uint32_t)(MBAR_BYTE + nxt * 8);
#pragma unroll
            for (int p = 0; p < CSZ; p++)
                mbar_arrive_rel_cluster(peer_base[p] + moff);
        }

        cur = nxt;
    }

    asm volatile("barrier.cluster.arrive.aligned;" ::: "memory");
    asm volatile("barrier.cluster.wait.aligned;"   ::: "memory");
}

// ============================================================================
// Kernel 3: out[b,t] = b_out + sum_c g_part[b][c][t]
// ============================================================================
__global__ __launch_bounds__(256)
void k_out(const float* __restrict__ b_out, float* __restrict__ out)
{
    int i = blockIdx.x * 256 + threadIdx.x;
    int b = i >> 9, t = i & 511;
    float s = b_out[0];
#pragma unroll
    for (int cc = 0; cc < CSZ; cc++) s += g_part[b * (CSZ * L_) + cc * L_ + t];
    out[i] = s;
}

// ============================================================================
extern "C" void kernel_launch(void* const* d_in, const int* in_sizes, int n_in,
                              void* d_out, int out_size)
{
    const float* obs  = (const float*)d_in[0];
    const float* act  = (const float*)d_in[1];
    const float* W_ci = (const float*)d_in[2];
    const float* b_ci = (const float*)d_in[3];
    const float* R    = (const float*)d_in[4];
    const float* bg   = (const float*)d_in[5];
    const float* W_o  = (const float*)d_in[6];
    const float* b_o  = (const float*)d_in[7];
    float* out = (float*)d_out;

    k_ci<<<dim3(8, 512), 256>>>(obs, act, W_ci, b_ci);

    cudaFuncSetAttribute(k_scan, cudaFuncAttributeMaxDynamicSharedMemorySize, SMEM_BYTES);
    k_scan<<<dim3(CSZ, NCL), THREADS, SMEM_BYTES>>>(R, bg, W_o);

    k_out<<<128, 256>>>(b_o, out);
}

// round 6
// speedup vs baseline: 2.5205x; 2.0268x over previous
#include <cuda_runtime.h>
#include <cstdint>

// Problem constants
#define B_ 64
#define L_ 512
#define P_ 64
#define A_ 16
#define F_ 80
#define D_ 512

// Scan organization
#define CSZ 8       // CTAs per cluster (column split of R)
#define NCL 16      // clusters (B_/ROWS)
#define ROWS 4      // batch rows per cluster
#define COLS 64     // columns per CTA
#define KROWS 32    // rows per warp k-slice (16 warps)
#define THREADS 512

// Scratch
__device__ float g_ci[B_ * L_ * D_];      // tanh(x@W_ci+b)
__device__ float g_part[B_ * CSZ * L_];   // per-CTA cumulative output partials

// ---- f32x2 helpers --------------------------------------------------------
__device__ __forceinline__ unsigned long long pk2(float lo, float hi) {
    unsigned long long r;
    asm("mov.b64 %0, {%1,%2};" : "=l"(r) : "f"(lo), "f"(hi));
    return r;
}
__device__ __forceinline__ void fma2(unsigned long long& d, unsigned long long a, unsigned long long b) {
    asm("fma.rn.f32x2 %0, %1, %2, %0;" : "+l"(d) : "l"(a), "l"(b));
}
__device__ __forceinline__ void upk2(float& lo, float& hi, unsigned long long v) {
    asm("mov.b64 {%0,%1}, %2;" : "=f"(lo), "=f"(hi) : "l"(v));
}

// ---- mbarrier / bulk-DSMEM helpers ----------------------------------------
__device__ __forceinline__ void mbar_init(uint32_t addr, uint32_t cnt) {
    asm volatile("mbarrier.init.shared.b64 [%0], %1;" :: "r"(addr), "r"(cnt) : "memory");
}
__device__ __forceinline__ void mbar_expect_tx(uint32_t addr, uint32_t bytes) {
    asm volatile("mbarrier.arrive.expect_tx.shared.b64 _, [%0], %1;"
                 :: "r"(addr), "r"(bytes) : "memory");
}
__device__ __forceinline__ void mbar_wait_cta(uint32_t addr, uint32_t parity) {
    uint32_t done;
    asm volatile(
        "{\n\t.reg .pred p;\n\t"
        "mbarrier.try_wait.parity.acquire.cta.shared::cta.b64 p, [%1], %2;\n\t"
        "selp.b32 %0, 1, 0, p;\n\t}"
        : "=r"(done) : "r"(addr), "r"(parity) : "memory");
    if (!done) {
        asm volatile(
            "{\n\t.reg .pred P1;\n\t"
            "WL_%=:\n\t"
            "mbarrier.try_wait.parity.acquire.cta.shared::cta.b64 P1, [%0], %1, 0x989680;\n\t"
            "@P1 bra.uni WD_%=;\n\t"
            "bra.uni WL_%=;\n\t"
            "WD_%=:\n\t}"
            :: "r"(addr), "r"(parity) : "memory");
    }
}
__device__ __forceinline__ void bulk_dsmem(uint32_t dst, uint32_t src,
                                           uint32_t bytes, uint32_t mbar) {
    asm volatile(
        "cp.async.bulk.shared::cluster.shared::cta.mbarrier::complete_tx::bytes "
        "[%0], [%1], %2, [%3];"
        :: "r"(dst), "r"(src), "r"(bytes), "r"(mbar) : "memory");
}
__device__ __forceinline__ void fence_proxy_async_cta() {
    asm volatile("fence.proxy.async.shared::cta;" ::: "memory");
}

// ============================================================================
// Kernel 1: ci = tanh(x @ W_ci + b_ci)
// ============================================================================
__global__ __launch_bounds__(256)
void k_ci(const float* __restrict__ obs, const float* __restrict__ act,
          const float* __restrict__ W, const float* __restrict__ bci)
{
    __shared__ float xs[64][81];
    __shared__ float ws[80][64];

    const int tid  = threadIdx.x;
    const int row0 = blockIdx.y * 64;
    const int d0   = blockIdx.x * 64;

    for (int idx = tid; idx < 64 * 80; idx += 256) {
        int r = idx / 80, c = idx % 80;
        int blg = row0 + r;
        int b = blg >> 9, l = blg & 511;
        xs[r][c] = (c < 64) ? obs[(b * L_ + l) * P_ + c]
                            : act[(b * L_ + l) * A_ + (c - 64)];
    }
    for (int idx = tid; idx < 80 * 64; idx += 256) {
        int k = idx >> 6, d = idx & 63;
        ws[k][d] = W[k * D_ + d0 + d];
    }
    __syncthreads();

    const int tx = tid & 15, ty = tid >> 4;
    float acc[4][4] = {};
#pragma unroll
    for (int k = 0; k < 80; k++) {
        float a0 = xs[ty * 4 + 0][k];
        float a1 = xs[ty * 4 + 1][k];
        float a2 = xs[ty * 4 + 2][k];
        float a3 = xs[ty * 4 + 3][k];
        float4 bv = *(const float4*)&ws[k][tx * 4];
        acc[0][0] += a0 * bv.x; acc[0][1] += a0 * bv.y; acc[0][2] += a0 * bv.z; acc[0][3] += a0 * bv.w;
        acc[1][0] += a1 * bv.x; acc[1][1] += a1 * bv.y; acc[1][2] += a1 * bv.z; acc[1][3] += a1 * bv.w;
        acc[2][0] += a2 * bv.x; acc[2][1] += a2 * bv.y; acc[2][2] += a2 * bv.z; acc[2][3] += a2 * bv.w;
        acc[3][0] += a3 * bv.x; acc[3][1] += a3 * bv.y; acc[3][2] += a3 * bv.z; acc[3][3] += a3 * bv.w;
    }

    float bi0 = bci[d0 + tx * 4 + 0];
    float bi1 = bci[d0 + tx * 4 + 1];
    float bi2 = bci[d0 + tx * 4 + 2];
    float bi3 = bci[d0 + tx * 4 + 3];
#pragma unroll
    for (int ii = 0; ii < 4; ii++) {
        int blg = row0 + ty * 4 + ii;
        float4 o;
        o.x = tanhf(acc[ii][0] + bi0);
        o.y = tanhf(acc[ii][1] + bi1);
        o.z = tanhf(acc[ii][2] + bi2);
        o.w = tanhf(acc[ii][3] + bi3);
        *(float4*)&g_ci[blg * D_ + d0 + tx * 4] = o;
    }
}

// ============================================================================
// Kernel 2: the scan. R in registers. Triple-buffered h delivered by
// cp.async.bulk DSMEM copies with mbarrier complete_tx (no fences, no
// arrive flood, 2 bars/step). hsta double-buffered (DMA source).
//
// SMEM (floats):
//   hbuf [0, 6144)        3 x 512 x 4   (h[i][b])
//   pbuf [6144, 10240)    512 x 8
//   hsta [10240, 10752)   2 x 64 x 4    (DMA source, per-parity)
//   bias [10752, 10816)
//   wsl  [10816, 10880)
//   osum [10880, 10912)
//   mbar @ byte 43648 (3 x 8 B)
// ============================================================================
#define HBUF_OFF  0
#define PBUF_OFF  6144
#define HSTA_OFF  10240
#define BIAS_OFF  10752
#define WSL_OFF   10816
#define OSUM_OFF  10880
#define MBAR_BYTE 43648
#define SMEM_BYTES (MBAR_BYTE + 64)

#define SLICE_BYTES (COLS * ROWS * 4)      // 1024
#define STEP_TX     (CSZ * SLICE_BYTES)    // 8192

extern __shared__ float smem_f[];

__global__ void __cluster_dims__(CSZ, 1, 1) __launch_bounds__(THREADS, 1)
k_scan(const float* __restrict__ R, const float* __restrict__ b_ig,
       const float* __restrict__ W_out)
{
    float* hbuf = smem_f + HBUF_OFF;
    float* pbuf = smem_f + PBUF_OFF;
    float* hsta = smem_f + HSTA_OFF;
    float* bias = smem_f + BIAS_OFF;
    float* wsl  = smem_f + WSL_OFF;
    float* osum = smem_f + OSUM_OFF;

    const uint32_t smem_u32 = (uint32_t)__cvta_generic_to_shared(smem_f);

    const int tid = threadIdx.x;
    const int c   = blockIdx.x;          // cluster rank / column slice
    const int b0  = blockIdx.y * ROWS;
    const int j0  = c * COLS;

    const int ks = tid >> 5;             // warp = k-slice (0..15)
    const int jp = tid & 31;             // column pair (cols 2jp, 2jp+1)
    const int jj = tid >> 2;             // reduce mapping (tid<256)
    const int bb = tid & 3;

    // ---- R slice into registers ----
    float rx[KROWS], ry[KROWS];
    {
        const float* rg = R + j0 + 2 * jp;
#pragma unroll
        for (int ii = 0; ii < KROWS; ii++) {
            float2 v = *(const float2*)(rg + (ks * KROWS + ii) * D_);
            rx[ii] = v.x; ry[ii] = v.y;
        }
    }

    // ---- init smem ----
    for (int idx = tid; idx < 3 * D_ * ROWS; idx += THREADS) hbuf[idx] = 0.0f;
    if (tid < COLS) {
        bias[tid] = b_ig[j0 + tid];
        wsl[tid]  = W_out[j0 + tid];
    }
    if (tid == 0) {
        mbar_init(smem_u32 + MBAR_BYTE + 0,  1);
        mbar_init(smem_u32 + MBAR_BYTE + 8,  1);
        mbar_init(smem_u32 + MBAR_BYTE + 16, 1);
    }
    __syncthreads();
    if (tid == 0) {
        // pre-post expect_tx for round 0 of each buffer (fills at t=0,1,2)
        mbar_expect_tx(smem_u32 + MBAR_BYTE + 0,  STEP_TX);
        mbar_expect_tx(smem_u32 + MBAR_BYTE + 8,  STEP_TX);
        mbar_expect_tx(smem_u32 + MBAR_BYTE + 16, STEP_TX);
    }
    __syncthreads();
    asm volatile("barrier.cluster.arrive.aligned;" ::: "memory");
    asm volatile("barrier.cluster.wait.aligned;"   ::: "memory");

    // Peer smem bases
    uint32_t peer_base[CSZ];
#pragma unroll
    for (int p = 0; p < CSZ; p++) {
        asm volatile("mapa.shared::cluster.u32 %0, %1, %2;"
                     : "=r"(peer_base[p]) : "r"(smem_u32), "r"(p));
    }

    float racc = 0.0f;
    int cur = 0;
    uint32_t phases = 0;   // bit b = next wait parity for buffer b

    for (int t = 0; t < L_; t++) {
        const int nxt = (cur == 2) ? 0 : cur + 1;

        // prefetch ci (consumed after matvec)
        float civ = 0.0f;
        if (tid < 256)
            civ = __ldg(&g_ci[((b0 + bb) * L_ + t) * D_ + j0 + jj]);

        // wait for h(t) delivery (skip t=0: zeros written locally)
        if (t > 0) {
            mbar_wait_cta(smem_u32 + MBAR_BYTE + cur * 8, (phases >> cur) & 1u);
            phases ^= (1u << cur);
            // re-post expect for this buffer's NEXT fill round (at step t+2)
            if (tid == 256)
                mbar_expect_tx(smem_u32 + MBAR_BYTE + cur * 8, STEP_TX);
        }

        const float* hc = hbuf + cur * (D_ * ROWS);

        // ---- matvec: R from registers, h broadcast from smem ----
        {
            const ulonglong2* hvp = (const ulonglong2*)(hc + ks * KROWS * ROWS);
            unsigned long long a00 = 0, a01 = 0, a10 = 0, a11 = 0;
#pragma unroll
            for (int ii = 0; ii < KROWS; ii++) {
                ulonglong2 hv = hvp[ii];
                unsigned long long r0 = pk2(rx[ii], rx[ii]);
                unsigned long long r1 = pk2(ry[ii], ry[ii]);
                fma2(a00, r0, hv.x); fma2(a01, r0, hv.y);
                fma2(a10, r1, hv.x); fma2(a11, r1, hv.y);
            }
            float4 q0, q1;
            upk2(q0.x, q0.y, a00); upk2(q0.z, q0.w, a01);
            upk2(q1.x, q1.y, a10); upk2(q1.z, q1.w, a11);
            float* pb = pbuf + (ks * 32 + jp) * 8;
            *(float4*)(pb)     = q0;
            *(float4*)(pb + 4) = q1;
        }
        __syncthreads();

        // ---- reduce + gate + update ----
        if (tid < 256) {
            float z = bias[jj];
#pragma unroll
            for (int s = 0; s < 16; s++) z += pbuf[s * 256 + tid];
            float ig = 1.0f / (1.0f + __expf(-z));
            float u  = civ * ig;
            float hval = hc[(j0 + jj) * 4 + bb] + u;
            hsta[(t & 1) * 256 + tid] = hval;

            float pp = u * wsl[jj];
            pp += __shfl_xor_sync(0xFFFFFFFF, pp, 4);
            pp += __shfl_xor_sync(0xFFFFFFFF, pp, 8);
            pp += __shfl_xor_sync(0xFFFFFFFF, pp, 16);
            if ((tid & 31) < 4)
                osum[(tid >> 5) * 4 + bb] = pp;
        }
        __syncthreads();

        // ---- DMA broadcast h(t+1): 8 threads, one bulk copy per peer ----
        if (t + 1 < L_ && tid < CSZ) {
            fence_proxy_async_cta();
            uint32_t src  = smem_u32 + (uint32_t)(HSTA_OFF + (t & 1) * 256) * 4u;
            uint32_t doff = (uint32_t)(HBUF_OFF + nxt * (D_ * ROWS)) * 4u
                          + (uint32_t)(c * SLICE_BYTES);
            uint32_t moff = (uint32_t)(MBAR_BYTE + nxt * 8);
            bulk_dsmem(peer_base[tid] + doff, src, SLICE_BYTES,
                       peer_base[tid] + moff);
        }

        // ---- cumulative output partial (parallel with DMA issue) ----
        if (tid < 4) {
            float s = 0.0f;
#pragma unroll
            for (int w = 0; w < 8; w++) s += osum[w * 4 + tid];
            racc += s;
            g_part[(b0 + tid) * (CSZ * L_) + c * L_ + t] = racc;
        }

        cur = nxt;
    }

    asm volatile("barrier.cluster.arrive.aligned;" ::: "memory");
    asm volatile("barrier.cluster.wait.aligned;"   ::: "memory");
}

// ============================================================================
// Kernel 3: out[b,t] = b_out + sum_c g_part[b][c][t]
// ============================================================================
__global__ __launch_bounds__(256)
void k_out(const float* __restrict__ b_out, float* __restrict__ out)
{
    int i = blockIdx.x * 256 + threadIdx.x;
    int b = i >> 9, t = i & 511;
    float s = b_out[0];
#pragma unroll
    for (int cc = 0; cc < CSZ; cc++) s += g_part[b * (CSZ * L_) + cc * L_ + t];
    out[i] = s;
}

// ============================================================================
extern "C" void kernel_launch(void* const* d_in, const int* in_sizes, int n_in,
                              void* d_out, int out_size)
{
    const float* obs  = (const float*)d_in[0];
    const float* act  = (const float*)d_in[1];
    const float* W_ci = (const float*)d_in[2];
    const float* b_ci = (const float*)d_in[3];
    const float* R    = (const float*)d_in[4];
    const float* bg   = (const float*)d_in[5];
    const float* W_o  = (const float*)d_in[6];
    const float* b_o  = (const float*)d_in[7];
    float* out = (float*)d_out;

    k_ci<<<dim3(8, 512), 256>>>(obs, act, W_ci, b_ci);

    cudaFuncSetAttribute(k_scan, cudaFuncAttributeMaxDynamicSharedMemorySize, SMEM_BYTES);
    k_scan<<<dim3(CSZ, NCL), THREADS, SMEM_BYTES>>>(R, bg, W_o);

    k_out<<<128, 256>>>(b_o, out);
}